// round 12
// baseline (speedup 1.0000x reference)
#include <cuda_runtime.h>
#include <cuda_fp16.h>
#include <cstdint>

#define H   2048
#define I   1408
#define E   8
#define T   512
#define I2  2816   // 2*I
#define IW  704    // I/2: act row width in uint32 (fp16 pairs)
#define HW  1024   // H/2: x row width in uint32 (fp16 pairs)

// gemm1 smem: A fp16 ring 3x8KB @0, B fp16 double 2x8KB @0x6000; epi stage 128*68*4
#define SMEM1    0xA000   // 40 KB
// gemm2 smem: A fp16 ring 3x8KB @0 (64 rows x 128B), B double 2x16KB @0x6000 (128 rows x 128B)
#define SMEM2    0xE000   // 56 KB; epilogue stage 64*132*4 = 33792 overlays

// ---------------- device scratch (no allocations allowed) ----------------
__device__ int   g_cnt[E];
__device__ int   g_tok[E][T];
__device__ float g_cw [E][T];
__device__ __align__(16) uint32_t g_act[(size_t)E * T * IW];  // fp16 pairs
__device__ __align__(16) uint32_t g_x  [(size_t)T * HW];      // fp16 pairs

// ---------------- helpers ----------------
__device__ __forceinline__ uint32_t smem_u32(const void* p) {
    uint32_t a;
    asm("{ .reg .u64 t; cvta.to.shared.u64 t, %1; cvt.u32.u64 %0, t; }" : "=r"(a) : "l"(p));
    return a;
}
// pack two fp32 -> fp16x2 (first arg in low 16 bits)
__device__ __forceinline__ uint32_t packh(float lo, float hi) {
    uint32_t r;
    asm("cvt.rn.f16x2.f32 %0, %1, %2;" : "=r"(r) : "f"(hi), "f"(lo));
    return r;
}
__device__ __forceinline__ void ldsm4(uint32_t* r, uint32_t a) {
    asm volatile("ldmatrix.sync.aligned.m8n8.x4.shared.b16 {%0,%1,%2,%3}, [%4];"
        : "=r"(r[0]), "=r"(r[1]), "=r"(r[2]), "=r"(r[3]) : "r"(a));
}
__device__ __forceinline__ void mma_h(float* d, const uint32_t* a, uint32_t b0, uint32_t b1) {
    asm volatile("mma.sync.aligned.m16n8k16.row.col.f32.f16.f16.f32 "
        "{%0,%1,%2,%3}, {%4,%5,%6,%7}, {%8,%9}, {%0,%1,%2,%3};"
        : "+f"(d[0]), "+f"(d[1]), "+f"(d[2]), "+f"(d[3])
        : "r"(a[0]), "r"(a[1]), "r"(a[2]), "r"(a[3]), "r"(b0), "r"(b1));
}
#define CP16(d_, s_)  asm volatile("cp.async.cg.shared.global [%0], [%1], 16;" :: "r"(d_), "l"(s_))
#define CPCOMMIT()    asm volatile("cp.async.commit_group;" ::)
#define CPWAIT(n_)    asm volatile("cp.async.wait_group %0;" :: "n"(n_))

// ---------------- init ----------------
__global__ void k_init() {
    if (threadIdx.x < E) g_cnt[threadIdx.x] = 0;
}

// ---------------- router: zero out row, convert x row to fp16, route ----------------
__global__ void k_router(const float* __restrict__ x, const float* __restrict__ wg,
                         float* __restrict__ out) {
    const int t = blockIdx.x, tid = threadIdx.x, w = tid >> 5, lane = tid & 31;
    const float* xr = x + (size_t)t * H;
    float4 z = make_float4(0.f, 0.f, 0.f, 0.f);
    *(float4*)(out + (size_t)t * H + tid * 4)        = z;
    *(float4*)(out + (size_t)t * H + 1024 + tid * 4) = z;
    #pragma unroll
    for (int i = tid * 4; i < H; i += 1024) {
        float4 v = *(const float4*)(xr + i);
        *(uint2*)(g_x + (size_t)t * HW + i / 2) =
            make_uint2(packh(v.x, v.y), packh(v.z, v.w));
    }
    const float* gr = wg + (size_t)w * H;
    float s = 0.f;
    for (int i = lane * 4; i < H; i += 128) {
        float4 xv = *(const float4*)(xr + i);
        float4 gv = *(const float4*)(gr + i);
        s += xv.x * gv.x + xv.y * gv.y + xv.z * gv.z + xv.w * gv.w;
    }
    #pragma unroll
    for (int o = 16; o; o >>= 1) s += __shfl_xor_sync(0xffffffffu, s, o);
    __shared__ float lg[E];
    if (lane == 0) lg[w] = s;
    __syncthreads();
    if (tid == 0) {
        float mx = lg[0];
        #pragma unroll
        for (int e = 1; e < E; e++) mx = fmaxf(mx, lg[e]);
        float ex[E];
        #pragma unroll
        for (int e = 0; e < E; e++) ex[e] = expf(lg[e] - mx);
        int i0 = 0;
        #pragma unroll
        for (int e = 1; e < E; e++) if (ex[e] > ex[i0]) i0 = e;
        int i1 = (i0 == 0) ? 1 : 0;
        #pragma unroll
        for (int e = 0; e < E; e++) if (e != i0 && ex[e] > ex[i1]) i1 = e;
        float s0 = ex[i0], s1 = ex[i1], inv = 1.f / (s0 + s1);
        int p0 = atomicAdd(&g_cnt[i0], 1);
        g_tok[i0][p0] = t;  g_cw[i0][p0] = s0 * inv;
        int p1 = atomicAdd(&g_cnt[i1], 1);
        g_tok[i1][p1] = t;  g_cw[i1][p1] = s1 * inv;
    }
}

// B prefetch: 16 floats per thread (2 thr/row over 128 rows)  [gemm1]
#define LDG_B(kt_)                                                              \
    { const float* p = bptr + (size_t)(kt_) * 32;                               \
      bv[0] = *(const float4*)p;       bv[1] = *(const float4*)(p + 4);         \
      bv[2] = *(const float4*)(p + 8); bv[3] = *(const float4*)(p + 12); }

// convert 16 fp32 -> 16 fp16, store two 16B chunks into 64B-row B tile  [gemm1]
#define STS_B(boff_)                                                            \
    { char* s = sm + (boff_);                                                   \
      uint32_t u[8];                                                            \
      _Pragma("unroll")                                                         \
      for (int i = 0; i < 4; i++) {                                             \
          u[2*i]   = packh(bv[i].x, bv[i].y);                                   \
          u[2*i+1] = packh(bv[i].z, bv[i].w);                                   \
      }                                                                         \
      *(uint4*)(s + b_sts0)        = make_uint4(u[0], u[1], u[2], u[3]);        \
      *(uint4*)(s + (b_sts0 ^ 16)) = make_uint4(u[4], u[5], u[6], u[7]);        \
    }

// ---------------- GEMM1: act = silu(x@Wg^T)*(x@Wu^T)  (R11 proven) ----------------
// block 128m x 128 B-rows, gate/up interleaved (even row=gate, odd=up -> 64 act cols)
// BK=32, 8 warps (2m x 4n), warp tile 64m x 32n
__global__ void __launch_bounds__(256, 2) k_gemm1(const float* __restrict__ w1) {
    const int e = blockIdx.z, cnt = g_cnt[e];
    const int m0 = blockIdx.y * 128;
    if (m0 >= cnt) return;
    const int n0 = blockIdx.x * 64;   // act col base

    extern __shared__ char sm[];
    const uint32_t sbase = smem_u32(sm);
    __shared__ int s_tok[128];

    const int tid = threadIdx.x, lane = tid & 31, wid = tid >> 5;
    if (tid < 128) { int r = m0 + tid; if (r >= cnt) r = cnt - 1; s_tok[tid] = g_tok[e][r]; }
    __syncthreads();

    // A loader: 2 thr/row over 128 rows, 32B each (two 16B chunks)
    const int lrow = tid >> 1, q = tid & 1;
    const uint32_t* arow = g_x + (size_t)s_tok[lrow] * HW;
    const uint32_t a_sw = (((uint32_t)lrow >> 1) & 3) << 4;
    const uint32_t a_d0 = (uint32_t)lrow * 64 + (((uint32_t)q * 32) ^ a_sw);
    const uint32_t a_d1 = (uint32_t)lrow * 64 + (((uint32_t)q * 32 + 16) ^ a_sw);
    // B loader: 2 thr/row over 128 interleaved rows (even=gate, odd=up)
    const int brow = tid >> 1, bh = tid & 1;
    const int wrow = (brow & 1) ? (I + n0 + (brow >> 1)) : (n0 + (brow >> 1));
    const float* bptr = w1 + ((size_t)e * I2 + wrow) * H + bh * 16;
    const uint32_t b_sts0 = (uint32_t)brow * 64 +
        (((uint32_t)bh << 5) ^ ((((uint32_t)brow >> 1) & 3) << 4));
    // fragment bases
    const int wm = (wid & 1) * 64, wn = (wid >> 1) * 32;
    const uint32_t a_row = wm + (lane & 15);
    const uint32_t a_swb = a_row * 64 +
        ((((uint32_t)lane >> 4) << 4) ^ (((a_row >> 1) & 3) << 4));
    const uint32_t b_row = wn + (lane & 7) + ((lane >> 4) << 3);
    const uint32_t b_swb = b_row * 64 +
        (((((uint32_t)lane >> 3) & 1) << 4) ^ (((b_row >> 1) & 3) << 4));

    float acc[4][4][4] = {};
    float4 bv[4];
    const int KT = H / 32;

    #define ISSUE_A1(kt_)                                                       \
        do {                                                                    \
            if ((kt_) < KT) {                                                   \
                uint32_t st = sbase + (((kt_) % 3) << 13);                      \
                const uint32_t* s = arow + (kt_) * 16 + q * 8;                  \
                CP16(st + a_d0, (const char*)s);                                \
                CP16(st + a_d1, (const char*)(s + 4));                          \
            }                                                                   \
            CPCOMMIT();                                                         \
        } while (0)

    ISSUE_A1(0);
    ISSUE_A1(1);
    LDG_B(0);
    STS_B(0x6000);

    for (int kt = 0; kt < KT; kt++) {
        if (kt + 1 < KT) LDG_B(kt + 1);
        CPWAIT(1);
        __syncthreads();
        ISSUE_A1(kt + 2);
        const uint32_t aoff = sbase + ((kt % 3) << 13);
        const uint32_t boff = sbase + 0x6000 + ((kt & 1) << 13);
        #pragma unroll
        for (int kk = 0; kk < 2; kk++) {
            uint32_t Ah[4][4], Bh[2][4];
            #pragma unroll
            for (int mt = 0; mt < 4; mt++)
                ldsm4(Ah[mt], aoff + ((a_swb + mt * 1024) ^ (kk << 5)));
            #pragma unroll
            for (int n2 = 0; n2 < 2; n2++)
                ldsm4(Bh[n2], boff + ((b_swb + n2 * 1024) ^ (kk << 5)));
            #pragma unroll
            for (int mt = 0; mt < 4; mt++)
                #pragma unroll
                for (int n2 = 0; n2 < 2; n2++) {
                    mma_h(acc[mt][2*n2],   Ah[mt], Bh[n2][0], Bh[n2][1]);
                    mma_h(acc[mt][2*n2+1], Ah[mt], Bh[n2][2], Bh[n2][3]);
                }
        }
        if (kt + 1 < KT) STS_B(0x6000 + (((kt + 1) & 1) << 13));
    }

    // epilogue: gate/up pairs adjacent in acc -> act in-register, stage [128][68] fp32
    CPWAIT(0);
    __syncthreads();
    float* stg = (float*)sm;
    #pragma unroll
    for (int mt = 0; mt < 4; mt++)
        #pragma unroll
        for (int nf = 0; nf < 4; nf++) {
            int r = wm + mt * 16 + (lane >> 2);
            int a = (wn >> 1) + nf * 4 + (lane & 3);
            float g0 = acc[mt][nf][0], u0 = acc[mt][nf][1];
            float g1 = acc[mt][nf][2], u1 = acc[mt][nf][3];
            stg[r * 68 + a]       = g0 / (1.f + __expf(-g0)) * u0;
            stg[(r + 8) * 68 + a] = g1 / (1.f + __expf(-g1)) * u1;
        }
    __syncthreads();
    const int erow = tid >> 1, grow = m0 + erow;
    if (grow < cnt) {
        const int pc = (tid & 1) * 32;
        uint32_t hw[16];
        #pragma unroll
        for (int j = 0; j < 16; j++) {
            int c0 = pc + 2 * j;
            hw[j] = packh(stg[erow * 68 + c0], stg[erow * 68 + c0 + 1]);
        }
        size_t base = ((size_t)e * T + grow) * IW + (n0 >> 1) + (pc >> 1);
        #pragma unroll
        for (int p4 = 0; p4 < 4; p4++)
            *(uint4*)(g_act + base + 4 * p4) =
                make_uint4(hw[4*p4], hw[4*p4+1], hw[4*p4+2], hw[4*p4+3]);
    }
    #undef ISSUE_A1
}

// ---------------- GEMM2: out[tok] += cw * (act @ W2^T) ----------------
// block 64m x 128n, BK=64, 8 warps = 2m x 2n x 2k (warp tile 32m x 64n, k-split 2)
// A/B tiles use 128B rows: chunk-rotation swizzle off = row*128 + (kbytes ^ ((row&7)<<4))
__global__ void __launch_bounds__(256, 2) k_gemm2(const float* __restrict__ w2,
                                                  float* __restrict__ out) {
    const int e = blockIdx.z, cnt = g_cnt[e];
    const int m0 = blockIdx.y * 64;
    if (m0 >= cnt) return;
    const int n0 = blockIdx.x * 128;

    extern __shared__ char sm[];
    const uint32_t sbase = smem_u32(sm);
    __shared__ int   s_tok[64];
    __shared__ float s_cw [64];

    const int tid = threadIdx.x, lane = tid & 31, wid = tid >> 5;
    if (tid < 64) {
        int r = m0 + tid, rr = (r < cnt) ? r : (cnt - 1);
        s_tok[tid] = g_tok[e][rr];
        s_cw [tid] = (r < cnt) ? g_cw[e][r] : 0.f;
    }
    __syncthreads();

    // A loader: 4 thr/row over 64 rows, 32B each (two 16B chunks); rows are 128B (64k fp16)
    const int lrow = tid >> 2, q4 = tid & 3;
    int ar = m0 + lrow; if (ar >= cnt) ar = cnt - 1;
    const uint32_t* arow = g_act + ((size_t)e * T + ar) * IW;
    const uint32_t a_rot = ((uint32_t)lrow & 7) << 4;
    const uint32_t a_d0 = (uint32_t)lrow * 128 + (((uint32_t)q4 * 32) ^ a_rot);
    const uint32_t a_d1 = (uint32_t)lrow * 128 + (((uint32_t)q4 * 32 + 16) ^ a_rot);
    // B loader: 2 thr/row over 128 rows; per kt 64 floats/row, thread covers 32 (two 16-float halves)
    const int brow = tid >> 1, bq = tid & 1;
    const float* bptr = w2 + ((size_t)e * H + n0 + brow) * I + bq * 32;
    const uint32_t b_rot = ((uint32_t)brow & 7) << 4;
    const uint32_t b_rowb = (uint32_t)brow * 128;

    // fragment bases: wg = k-half, (wid&1) = m, ((wid>>1)&1) = n
    const int wg = wid >> 2;
    const int wm = (wid & 1) * 32, wn = ((wid >> 1) & 1) * 64;
    const uint32_t kbase = (uint32_t)wg * 64;   // byte offset of this wg's k-half in a row
    const uint32_t a_row = wm + (lane & 15);
    const uint32_t a_rowb = a_row * 128;
    const uint32_t a_rotf = (a_row & 7) << 4;
    const uint32_t a_chk = ((uint32_t)lane >> 4) << 4;
    const uint32_t b_row = wn + (lane & 7) + ((lane >> 4) << 3);
    const uint32_t b_rotf = (b_row & 7) << 4;
    const uint32_t b_chk = (((uint32_t)lane >> 3) & 1) << 4;

    float acc[2][8][4] = {};
    float4 bv[4];
    const int KT = I / 64;   // 22

    #define ISSUE_A2(kt_)                                                       \
        do {                                                                    \
            if ((kt_) < KT) {                                                   \
                uint32_t st = sbase + (((kt_) % 3) << 13);                      \
                const uint32_t* s = arow + (kt_) * 32 + q4 * 8;                 \
                CP16(st + a_d0, (const char*)s);                                \
                CP16(st + a_d1, (const char*)(s + 4));                          \
            }                                                                   \
            CPCOMMIT();                                                         \
        } while (0)

    #define LDG_BH2(kt_, h_)                                                    \
        { const float* p = bptr + (size_t)(kt_) * 64 + (h_) * 16;               \
          bv[0] = *(const float4*)p;       bv[1] = *(const float4*)(p + 4);     \
          bv[2] = *(const float4*)(p + 8); bv[3] = *(const float4*)(p + 12); }

    #define STS_BH2(b_, h_)                                                     \
        { char* s = sm + 0x6000 + ((b_) << 14);                                 \
          uint32_t u[8];                                                        \
          _Pragma("unroll")                                                     \
          for (int i = 0; i < 4; i++) {                                         \
              u[2*i]   = packh(bv[i].x, bv[i].y);                               \
              u[2*i+1] = packh(bv[i].z, bv[i].w);                               \
          }                                                                     \
          uint32_t o = (uint32_t)bq * 64 + (h_) * 32;                           \
          *(uint4*)(s + b_rowb + (o ^ b_rot))        = make_uint4(u[0], u[1], u[2], u[3]); \
          *(uint4*)(s + b_rowb + ((o + 16) ^ b_rot)) = make_uint4(u[4], u[5], u[6], u[7]); \
        }

    ISSUE_A2(0);
    ISSUE_A2(1);
    LDG_BH2(0, 0);  STS_BH2(0, 0);
    LDG_BH2(0, 1);  STS_BH2(0, 1);

    for (int kt = 0; kt < KT; kt++) {
        if (kt + 1 < KT) LDG_BH2(kt + 1, 0);
        CPWAIT(1);
        __syncthreads();
        ISSUE_A2(kt + 2);
        const uint32_t aoff = sbase + ((kt % 3) << 13);
        const uint32_t boff = sbase + 0x6000 + ((kt & 1) << 14);
        #pragma unroll
        for (int kk = 0; kk < 2; kk++) {
            uint32_t Ah[2][4], Bh[4][4];
            const uint32_t ko = kbase + (kk << 5);
            #pragma unroll
            for (int mt = 0; mt < 2; mt++)
                ldsm4(Ah[mt], aoff + a_rowb + mt * 2048 + ((ko + a_chk) ^ a_rotf));
            #pragma unroll
            for (int n2 = 0; n2 < 4; n2++)
                ldsm4(Bh[n2], boff + b_row * 128 + n2 * 2048 + ((ko + b_chk) ^ b_rotf));
            #pragma unroll
            for (int mt = 0; mt < 2; mt++)
                #pragma unroll
                for (int n2 = 0; n2 < 4; n2++) {
                    mma_h(acc[mt][2*n2],   Ah[mt], Bh[n2][0], Bh[n2][1]);
                    mma_h(acc[mt][2*n2+1], Ah[mt], Bh[n2][2], Bh[n2][3]);
                }
            if (kk == 0 && kt + 1 < KT) { STS_BH2((kt + 1) & 1, 0); LDG_BH2(kt + 1, 1); }
        }
        if (kt + 1 < KT) STS_BH2((kt + 1) & 1, 1);
    }
    CPWAIT(0);
    __syncthreads();

    // ---- k-split merge + coalesced epilogue via stage [64][132] fp32 ----
    float* stg = (float*)sm;
    if (wg == 1) {
        #pragma unroll
        for (int mt = 0; mt < 2; mt++)
            #pragma unroll
            for (int nf = 0; nf < 8; nf++) {
                int r = wm + mt * 16 + (lane >> 2);
                int c = wn + nf * 8 + (lane & 3) * 2;
                stg[r * 132 + c]           = acc[mt][nf][0];
                stg[r * 132 + c + 1]       = acc[mt][nf][1];
                stg[(r + 8) * 132 + c]     = acc[mt][nf][2];
                stg[(r + 8) * 132 + c + 1] = acc[mt][nf][3];
            }
    }
    __syncthreads();
    if (wg == 0) {
        #pragma unroll
        for (int mt = 0; mt < 2; mt++)
            #pragma unroll
            for (int nf = 0; nf < 8; nf++) {
                int r = wm + mt * 16 + (lane >> 2);
                int c = wn + nf * 8 + (lane & 3) * 2;
                float cw0 = s_cw[r], cw1 = s_cw[r + 8];
                float v0 = (acc[mt][nf][0] + stg[r * 132 + c])           * cw0;
                float v1 = (acc[mt][nf][1] + stg[r * 132 + c + 1])       * cw0;
                float v2 = (acc[mt][nf][2] + stg[(r + 8) * 132 + c])     * cw1;
                float v3 = (acc[mt][nf][3] + stg[(r + 8) * 132 + c + 1]) * cw1;
                stg[r * 132 + c]           = v0;
                stg[r * 132 + c + 1]       = v1;
                stg[(r + 8) * 132 + c]     = v2;
                stg[(r + 8) * 132 + c + 1] = v3;
            }
    }
    __syncthreads();
    // all 256 threads: coalesced atomicAdd, 4 consecutive cols x 8 rows each
    #pragma unroll
    for (int i = 0; i < 8; i++) {
        int r = (tid >> 5) + i * 8;
        if (m0 + r < cnt) {
            float4 v = *(float4*)(stg + r * 132 + lane * 4);
            float* op = out + (size_t)s_tok[r] * H + n0 + lane * 4;
            atomicAdd(op,     v.x);
            atomicAdd(op + 1, v.y);
            atomicAdd(op + 2, v.z);
            atomicAdd(op + 3, v.w);
        }
    }
    #undef ISSUE_A2
    #undef LDG_BH2
    #undef STS_BH2
}

// ---------------- launch ----------------
extern "C" void kernel_launch(void* const* d_in, const int* in_sizes, int n_in,
                              void* d_out, int out_size) {
    const float* x  = (const float*)d_in[0];   // [T, H]
    const float* w1 = (const float*)d_in[1];   // [E, 2I, H]
    const float* w2 = (const float*)d_in[2];   // [E, H, I]
    const float* wg = (const float*)d_in[3];   // [E, H]
    float* out = (float*)d_out;                // [T, 1, H]

    cudaFuncSetAttribute(k_gemm1, cudaFuncAttributeMaxDynamicSharedMemorySize, SMEM1);
    cudaFuncSetAttribute(k_gemm2, cudaFuncAttributeMaxDynamicSharedMemorySize, SMEM2);

    k_init<<<1, 32>>>();
    k_router<<<T, 256>>>(x, wg, out);
    k_gemm1<<<dim3(I / 64, (T + 127) / 128, E), 256, SMEM1>>>(w1);
    k_gemm2<<<dim3(H / 128, (T + 63) / 64, E), 256, SMEM2>>>(w2, out);
}

// round 13
// speedup vs baseline: 1.1368x; 1.1368x over previous
#include <cuda_runtime.h>
#include <cuda_fp16.h>
#include <cstdint>

#define H   2048
#define I   1408
#define E   8
#define T   512
#define I2  2816   // 2*I
#define IW  704    // I/2: act row width in uint32 (fp16 pairs)
#define HW  1024   // H/2: x row width in uint32 (fp16 pairs)

// gemm1 smem: A fp16 ring 3x8KB @0, B fp16 double 2x8KB @0x6000; epi stage 128*68*4
#define SMEM1    0xA000   // 40 KB
// gemm2 smem: A fp16 ring 3x4KB @0, B fp16 double 2x8KB @0x3000; epi stage 64*132*4 = 33792
#define SMEM2    0x8400   // 33 KB
// ---------------- device scratch (no allocations allowed) ----------------
__device__ int   g_cnt[E];
__device__ int   g_tok[E][T];
__device__ float g_cw [E][T];
__device__ __align__(16) uint32_t g_act[(size_t)E * T * IW];  // fp16 pairs
__device__ __align__(16) uint32_t g_x  [(size_t)T * HW];      // fp16 pairs

// ---------------- helpers ----------------
__device__ __forceinline__ uint32_t smem_u32(const void* p) {
    uint32_t a;
    asm("{ .reg .u64 t; cvta.to.shared.u64 t, %1; cvt.u32.u64 %0, t; }" : "=r"(a) : "l"(p));
    return a;
}
// pack two fp32 -> fp16x2 (first arg in low 16 bits)
__device__ __forceinline__ uint32_t packh(float lo, float hi) {
    uint32_t r;
    asm("cvt.rn.f16x2.f32 %0, %1, %2;" : "=r"(r) : "f"(hi), "f"(lo));
    return r;
}
__device__ __forceinline__ void ldsm4(uint32_t* r, uint32_t a) {
    asm volatile("ldmatrix.sync.aligned.m8n8.x4.shared.b16 {%0,%1,%2,%3}, [%4];"
        : "=r"(r[0]), "=r"(r[1]), "=r"(r[2]), "=r"(r[3]) : "r"(a));
}
__device__ __forceinline__ void mma_h(float* d, const uint32_t* a, uint32_t b0, uint32_t b1) {
    asm volatile("mma.sync.aligned.m16n8k16.row.col.f32.f16.f16.f32 "
        "{%0,%1,%2,%3}, {%4,%5,%6,%7}, {%8,%9}, {%0,%1,%2,%3};"
        : "+f"(d[0]), "+f"(d[1]), "+f"(d[2]), "+f"(d[3])
        : "r"(a[0]), "r"(a[1]), "r"(a[2]), "r"(a[3]), "r"(b0), "r"(b1));
}
#define CP16(d_, s_)  asm volatile("cp.async.cg.shared.global [%0], [%1], 16;" :: "r"(d_), "l"(s_))
#define CPCOMMIT()    asm volatile("cp.async.commit_group;" ::)
#define CPWAIT(n_)    asm volatile("cp.async.wait_group %0;" :: "n"(n_))

// ---------------- init ----------------
__global__ void k_init() {
    if (threadIdx.x < E) g_cnt[threadIdx.x] = 0;
}

// ---------------- router: zero out row, convert x row to fp16, route ----------------
__global__ void k_router(const float* __restrict__ x, const float* __restrict__ wg,
                         float* __restrict__ out) {
    const int t = blockIdx.x, tid = threadIdx.x, w = tid >> 5, lane = tid & 31;
    const float* xr = x + (size_t)t * H;
    float4 z = make_float4(0.f, 0.f, 0.f, 0.f);
    *(float4*)(out + (size_t)t * H + tid * 4)        = z;
    *(float4*)(out + (size_t)t * H + 1024 + tid * 4) = z;
    #pragma unroll
    for (int i = tid * 4; i < H; i += 1024) {
        float4 v = *(const float4*)(xr + i);
        *(uint2*)(g_x + (size_t)t * HW + i / 2) =
            make_uint2(packh(v.x, v.y), packh(v.z, v.w));
    }
    const float* gr = wg + (size_t)w * H;
    float s = 0.f;
    for (int i = lane * 4; i < H; i += 128) {
        float4 xv = *(const float4*)(xr + i);
        float4 gv = *(const float4*)(gr + i);
        s += xv.x * gv.x + xv.y * gv.y + xv.z * gv.z + xv.w * gv.w;
    }
    #pragma unroll
    for (int o = 16; o; o >>= 1) s += __shfl_xor_sync(0xffffffffu, s, o);
    __shared__ float lg[E];
    if (lane == 0) lg[w] = s;
    __syncthreads();
    if (tid == 0) {
        float mx = lg[0];
        #pragma unroll
        for (int e = 1; e < E; e++) mx = fmaxf(mx, lg[e]);
        float ex[E];
        #pragma unroll
        for (int e = 0; e < E; e++) ex[e] = expf(lg[e] - mx);
        int i0 = 0;
        #pragma unroll
        for (int e = 1; e < E; e++) if (ex[e] > ex[i0]) i0 = e;
        int i1 = (i0 == 0) ? 1 : 0;
        #pragma unroll
        for (int e = 0; e < E; e++) if (e != i0 && ex[e] > ex[i1]) i1 = e;
        float s0 = ex[i0], s1 = ex[i1], inv = 1.f / (s0 + s1);
        int p0 = atomicAdd(&g_cnt[i0], 1);
        g_tok[i0][p0] = t;  g_cw[i0][p0] = s0 * inv;
        int p1 = atomicAdd(&g_cnt[i1], 1);
        g_tok[i1][p1] = t;  g_cw[i1][p1] = s1 * inv;
    }
}

// B prefetch: 16 floats per thread (2 thr/row over 128 rows)
#define LDG_B(kt_)                                                              \
    { const float* p = bptr + (size_t)(kt_) * 32;                               \
      bv[0] = *(const float4*)p;       bv[1] = *(const float4*)(p + 4);         \
      bv[2] = *(const float4*)(p + 8); bv[3] = *(const float4*)(p + 12); }

// convert 16 fp32 -> 16 fp16, store two 16B chunks into 64B-row B tile
#define STS_B(boff_)                                                            \
    { char* s = sm + (boff_);                                                   \
      uint32_t u[8];                                                            \
      _Pragma("unroll")                                                         \
      for (int i = 0; i < 4; i++) {                                             \
          u[2*i]   = packh(bv[i].x, bv[i].y);                                   \
          u[2*i+1] = packh(bv[i].z, bv[i].w);                                   \
      }                                                                         \
      *(uint4*)(s + b_sts0)        = make_uint4(u[0], u[1], u[2], u[3]);        \
      *(uint4*)(s + (b_sts0 ^ 16)) = make_uint4(u[4], u[5], u[6], u[7]);        \
    }

// ---------------- GEMM1: act = silu(x@Wg^T)*(x@Wu^T)  (R11 proven) ----------------
// block 128m x 128 B-rows, gate/up interleaved (even row=gate, odd=up -> 64 act cols)
// BK=32, 8 warps (2m x 4n), warp tile 64m x 32n
__global__ void __launch_bounds__(256, 2) k_gemm1(const float* __restrict__ w1) {
    const int e = blockIdx.z, cnt = g_cnt[e];
    const int m0 = blockIdx.y * 128;
    if (m0 >= cnt) return;
    const int n0 = blockIdx.x * 64;   // act col base

    extern __shared__ char sm[];
    const uint32_t sbase = smem_u32(sm);
    __shared__ int s_tok[128];

    const int tid = threadIdx.x, lane = tid & 31, wid = tid >> 5;
    if (tid < 128) { int r = m0 + tid; if (r >= cnt) r = cnt - 1; s_tok[tid] = g_tok[e][r]; }
    __syncthreads();

    // A loader: 2 thr/row over 128 rows, 32B each (two 16B chunks)
    const int lrow = tid >> 1, q = tid & 1;
    const uint32_t* arow = g_x + (size_t)s_tok[lrow] * HW;
    const uint32_t a_sw = (((uint32_t)lrow >> 1) & 3) << 4;
    const uint32_t a_d0 = (uint32_t)lrow * 64 + (((uint32_t)q * 32) ^ a_sw);
    const uint32_t a_d1 = (uint32_t)lrow * 64 + (((uint32_t)q * 32 + 16) ^ a_sw);
    // B loader: 2 thr/row over 128 interleaved rows (even=gate, odd=up)
    const int brow = tid >> 1, bh = tid & 1;
    const int wrow = (brow & 1) ? (I + n0 + (brow >> 1)) : (n0 + (brow >> 1));
    const float* bptr = w1 + ((size_t)e * I2 + wrow) * H + bh * 16;
    const uint32_t b_sts0 = (uint32_t)brow * 64 +
        (((uint32_t)bh << 5) ^ ((((uint32_t)brow >> 1) & 3) << 4));
    // fragment bases
    const int wm = (wid & 1) * 64, wn = (wid >> 1) * 32;
    const uint32_t a_row = wm + (lane & 15);
    const uint32_t a_swb = a_row * 64 +
        ((((uint32_t)lane >> 4) << 4) ^ (((a_row >> 1) & 3) << 4));
    const uint32_t b_row = wn + (lane & 7) + ((lane >> 4) << 3);
    const uint32_t b_swb = b_row * 64 +
        (((((uint32_t)lane >> 3) & 1) << 4) ^ (((b_row >> 1) & 3) << 4));

    float acc[4][4][4] = {};
    float4 bv[4];
    const int KT = H / 32;

    #define ISSUE_A1(kt_)                                                       \
        do {                                                                    \
            if ((kt_) < KT) {                                                   \
                uint32_t st = sbase + (((kt_) % 3) << 13);                      \
                const uint32_t* s = arow + (kt_) * 16 + q * 8;                  \
                CP16(st + a_d0, (const char*)s);                                \
                CP16(st + a_d1, (const char*)(s + 4));                          \
            }                                                                   \
            CPCOMMIT();                                                         \
        } while (0)

    ISSUE_A1(0);
    ISSUE_A1(1);
    LDG_B(0);
    STS_B(0x6000);

    for (int kt = 0; kt < KT; kt++) {
        if (kt + 1 < KT) LDG_B(kt + 1);
        CPWAIT(1);
        __syncthreads();
        ISSUE_A1(kt + 2);
        const uint32_t aoff = sbase + ((kt % 3) << 13);
        const uint32_t boff = sbase + 0x6000 + ((kt & 1) << 13);
        #pragma unroll
        for (int kk = 0; kk < 2; kk++) {
            uint32_t Ah[4][4], Bh[2][4];
            #pragma unroll
            for (int mt = 0; mt < 4; mt++)
                ldsm4(Ah[mt], aoff + ((a_swb + mt * 1024) ^ (kk << 5)));
            #pragma unroll
            for (int n2 = 0; n2 < 2; n2++)
                ldsm4(Bh[n2], boff + ((b_swb + n2 * 1024) ^ (kk << 5)));
            #pragma unroll
            for (int mt = 0; mt < 4; mt++)
                #pragma unroll
                for (int n2 = 0; n2 < 2; n2++) {
                    mma_h(acc[mt][2*n2],   Ah[mt], Bh[n2][0], Bh[n2][1]);
                    mma_h(acc[mt][2*n2+1], Ah[mt], Bh[n2][2], Bh[n2][3]);
                }
        }
        if (kt + 1 < KT) STS_B(0x6000 + (((kt + 1) & 1) << 13));
    }

    // epilogue: gate/up pairs adjacent in acc -> act in-register, stage [128][68] fp32
    CPWAIT(0);
    __syncthreads();
    float* stg = (float*)sm;
    #pragma unroll
    for (int mt = 0; mt < 4; mt++)
        #pragma unroll
        for (int nf = 0; nf < 4; nf++) {
            int r = wm + mt * 16 + (lane >> 2);
            int a = (wn >> 1) + nf * 4 + (lane & 3);
            float g0 = acc[mt][nf][0], u0 = acc[mt][nf][1];
            float g1 = acc[mt][nf][2], u1 = acc[mt][nf][3];
            stg[r * 68 + a]       = g0 / (1.f + __expf(-g0)) * u0;
            stg[(r + 8) * 68 + a] = g1 / (1.f + __expf(-g1)) * u1;
        }
    __syncthreads();
    const int erow = tid >> 1, grow = m0 + erow;
    if (grow < cnt) {
        const int pc = (tid & 1) * 32;
        uint32_t hw[16];
        #pragma unroll
        for (int j = 0; j < 16; j++) {
            int c0 = pc + 2 * j;
            hw[j] = packh(stg[erow * 68 + c0], stg[erow * 68 + c0 + 1]);
        }
        size_t base = ((size_t)e * T + grow) * IW + (n0 >> 1) + (pc >> 1);
        #pragma unroll
        for (int p4 = 0; p4 < 4; p4++)
            *(uint4*)(g_act + base + 4 * p4) =
                make_uint4(hw[4*p4], hw[4*p4+1], hw[4*p4+2], hw[4*p4+3]);
    }
    #undef ISSUE_A1
}

// ---------------- GEMM2: out[tok] += cw * (act @ W2^T) ----------------
// block 64m x 128n, BK=32, 8 warps = 2m x 2n x 2k (warp tile 32m x 64n x 16k)
// loaders, tiles, swizzles identical to R11; only warp decomposition + epilogue changed
__global__ void __launch_bounds__(256, 2) k_gemm2(const float* __restrict__ w2,
                                                  float* __restrict__ out) {
    const int e = blockIdx.z, cnt = g_cnt[e];
    const int m0 = blockIdx.y * 64;
    if (m0 >= cnt) return;
    const int n0 = blockIdx.x * 128;

    extern __shared__ char sm[];
    const uint32_t sbase = smem_u32(sm);
    __shared__ int   s_tok[64];
    __shared__ float s_cw [64];

    const int tid = threadIdx.x, lane = tid & 31, wid = tid >> 5;
    if (tid < 64) {
        int r = m0 + tid, rr = (r < cnt) ? r : (cnt - 1);
        s_tok[tid] = g_tok[e][rr];
        s_cw [tid] = (r < cnt) ? g_cw[e][r] : 0.f;
    }
    __syncthreads();

    // A loader: 4 thr/row over 64 rows, 16B each (R11 proven)
    const int lrow = tid >> 2, q = tid & 3;
    int ar = m0 + lrow; if (ar >= cnt) ar = cnt - 1;
    const uint32_t* arow = g_act + ((size_t)e * T + ar) * IW;
    const uint32_t a_dst0 = (uint32_t)lrow * 64 +
        (((uint32_t)q * 16) ^ ((((uint32_t)lrow >> 1) & 3) << 4));
    // B loader: 2 thr/row over 128 rows (R11 proven)
    const int brow = tid >> 1, bh = tid & 1;
    const float* bptr = w2 + ((size_t)e * H + n0 + brow) * I + bh * 16;
    const uint32_t b_sts0 = (uint32_t)brow * 64 +
        (((uint32_t)bh << 5) ^ ((((uint32_t)brow >> 1) & 3) << 4));

    // warp decomposition: wg = k-half (fixed kk), (wid&1) = m, ((wid>>1)&1) = n
    const int wg = wid >> 2;
    const int wm = (wid & 1) * 32, wn = ((wid >> 1) & 1) * 64;
    const uint32_t kko = (uint32_t)wg << 5;   // fixed 32B k-chunk select
    const uint32_t a_row = wm + (lane & 15);
    const uint32_t a_swb = a_row * 64 +
        ((((uint32_t)lane >> 4) << 4) ^ (((a_row >> 1) & 3) << 4));
    const uint32_t b_row = wn + (lane & 7) + ((lane >> 4) << 3);
    const uint32_t b_swb = b_row * 64 +
        (((((uint32_t)lane >> 3) & 1) << 4) ^ (((b_row >> 1) & 3) << 4));

    float acc[2][8][4] = {};
    float4 bv[4];
    const int KT = I / 32;

    #define ISSUE_A2(kt_)                                                       \
        do {                                                                    \
            if ((kt_) < KT) {                                                   \
                uint32_t da = sbase + (((kt_) % 3) << 12) + a_dst0;             \
                CP16(da, (const char*)(arow + (kt_) * 16 + q * 4));             \
            }                                                                   \
            CPCOMMIT();                                                         \
        } while (0)

    ISSUE_A2(0);
    ISSUE_A2(1);
    LDG_B(0);
    STS_B(0x3000);

    for (int kt = 0; kt < KT; kt++) {
        if (kt + 1 < KT) LDG_B(kt + 1);
        CPWAIT(1);
        __syncthreads();
        ISSUE_A2(kt + 2);
        const uint32_t aoff = sbase + ((kt % 3) << 12);
        const uint32_t boff = sbase + 0x3000 + ((kt & 1) << 13);
        uint32_t Ah[2][4], Bh[4][4];
        #pragma unroll
        for (int mt = 0; mt < 2; mt++)
            ldsm4(Ah[mt], aoff + ((a_swb + mt * 1024) ^ kko));
        #pragma unroll
        for (int n2 = 0; n2 < 4; n2++)
            ldsm4(Bh[n2], boff + ((b_swb + n2 * 1024) ^ kko));
        #pragma unroll
        for (int mt = 0; mt < 2; mt++)
            #pragma unroll
            for (int n2 = 0; n2 < 4; n2++) {
                mma_h(acc[mt][2*n2],   Ah[mt], Bh[n2][0], Bh[n2][1]);
                mma_h(acc[mt][2*n2+1], Ah[mt], Bh[n2][2], Bh[n2][3]);
            }
        if (kt + 1 < KT) STS_B(0x3000 + (((kt + 1) & 1) << 13));
    }
    CPWAIT(0);
    __syncthreads();

    // ---- k-split merge + coalesced epilogue via stage [64][132] fp32 ----
    float* stg = (float*)sm;
    if (wg == 1) {
        #pragma unroll
        for (int mt = 0; mt < 2; mt++)
            #pragma unroll
            for (int nf = 0; nf < 8; nf++) {
                int r = wm + mt * 16 + (lane >> 2);
                int c = wn + nf * 8 + (lane & 3) * 2;
                stg[r * 132 + c]           = acc[mt][nf][0];
                stg[r * 132 + c + 1]       = acc[mt][nf][1];
                stg[(r + 8) * 132 + c]     = acc[mt][nf][2];
                stg[(r + 8) * 132 + c + 1] = acc[mt][nf][3];
            }
    }
    __syncthreads();
    if (wg == 0) {
        #pragma unroll
        for (int mt = 0; mt < 2; mt++)
            #pragma unroll
            for (int nf = 0; nf < 8; nf++) {
                int r = wm + mt * 16 + (lane >> 2);
                int c = wn + nf * 8 + (lane & 3) * 2;
                float cw0 = s_cw[r], cw1 = s_cw[r + 8];
                stg[r * 132 + c]           = (acc[mt][nf][0] + stg[r * 132 + c])           * cw0;
                stg[r * 132 + c + 1]       = (acc[mt][nf][1] + stg[r * 132 + c + 1])       * cw0;
                stg[(r + 8) * 132 + c]     = (acc[mt][nf][2] + stg[(r + 8) * 132 + c])     * cw1;
                stg[(r + 8) * 132 + c + 1] = (acc[mt][nf][3] + stg[(r + 8) * 132 + c + 1]) * cw1;
            }
    }
    __syncthreads();
    // all 256 threads: coalesced atomicAdd, 4 consecutive cols x 8 rows each
    #pragma unroll
    for (int i = 0; i < 8; i++) {
        int r = (tid >> 5) + i * 8;
        if (m0 + r < cnt) {
            float4 v = *(float4*)(stg + r * 132 + lane * 4);
            float* op = out + (size_t)s_tok[r] * H + n0 + lane * 4;
            atomicAdd(op,     v.x);
            atomicAdd(op + 1, v.y);
            atomicAdd(op + 2, v.z);
            atomicAdd(op + 3, v.w);
        }
    }
    #undef ISSUE_A2
}

// ---------------- launch ----------------
extern "C" void kernel_launch(void* const* d_in, const int* in_sizes, int n_in,
                              void* d_out, int out_size) {
    const float* x  = (const float*)d_in[0];   // [T, H]
    const float* w1 = (const float*)d_in[1];   // [E, 2I, H]
    const float* w2 = (const float*)d_in[2];   // [E, H, I]
    const float* wg = (const float*)d_in[3];   // [E, H]
    float* out = (float*)d_out;                // [T, 1, H]

    cudaFuncSetAttribute(k_gemm1, cudaFuncAttributeMaxDynamicSharedMemorySize, SMEM1);
    cudaFuncSetAttribute(k_gemm2, cudaFuncAttributeMaxDynamicSharedMemorySize, SMEM2);

    k_init<<<1, 32>>>();
    k_router<<<T, 256>>>(x, wg, out);
    k_gemm1<<<dim3(I / 64, (T + 127) / 128, E), 256, SMEM1>>>(w1);
    k_gemm2<<<dim3(H / 128, (T + 63) / 64, E), 256, SMEM2>>>(w2, out);
}